// round 16
// baseline (speedup 1.0000x reference)
#include <cuda_runtime.h>
#include <cuda_bf16.h>
#include <math.h>
#include <float.h>
#include <stdint.h>

#define VOCAB 30000
#define EMB   300
#define FEAT  2048
#define BATCH 256
#define NQ    32
#define NW    12
#define NK    64

#define KPAD  320
#define NPADB 320

// ---------------- scratch (static device globals; no runtime alloc) ----------
__device__ float g_P[(size_t)BATCH * NQ * KPAD];
__device__ float g_bc[NPADB];
#define BPK_WORDS (32 * 320 * 4 * 8)
__device__ __align__(16) uint32_t g_Bh[BPK_WORDS];
__device__ __align__(16) uint32_t g_Bl[BPK_WORDS];
#define WCPK_WORDS (5 * 320 * 4 * 8)
__device__ __align__(16) uint32_t g_Wch[WCPK_WORDS];
__device__ __align__(16) uint32_t g_Wcl[WCPK_WORDS];
#define WV_WORDS ((size_t)VOCAB * 160)
__device__ __align__(16) uint32_t g_wvh[WV_WORDS];
__device__ __align__(16) uint32_t g_wvl[WV_WORDS];
#define F_WORDS ((size_t)BATCH * NK * 1024)
__device__ __align__(16) uint32_t g_Fh[F_WORDS];
__device__ __align__(16) uint32_t g_Fl[F_WORDS];

// ======================= portable PTX helpers ================================
__device__ __forceinline__ uint32_t smem_u32(const void* p) {
    uint32_t a;
    asm("{ .reg .u64 t; cvta.to.shared.u64 t, %1; cvt.u32.u64 %0, t; }" : "=r"(a) : "l"(p));
    return a;
}
__device__ __forceinline__ void cp16(uint32_t s, const void* g) {
    asm volatile("cp.async.cg.shared.global [%0], [%1], 16;" :: "r"(s), "l"(g) : "memory");
}
__device__ __forceinline__ void mma_bf16(float* c, uint32_t a0, uint32_t a1,
                                         uint32_t a2, uint32_t a3,
                                         uint32_t b0, uint32_t b1) {
    asm volatile(
        "mma.sync.aligned.m16n8k16.row.col.f32.bf16.bf16.f32 "
        "{%0,%1,%2,%3}, {%4,%5,%6,%7}, {%8,%9}, {%0,%1,%2,%3};"
        : "+f"(c[0]), "+f"(c[1]), "+f"(c[2]), "+f"(c[3])
        : "r"(a0), "r"(a1), "r"(a2), "r"(a3), "r"(b0), "r"(b1));
}
__device__ __forceinline__ uint32_t pack_bf2(float x, float y) {
    return (uint32_t)__bfloat16_as_ushort(__float2bfloat16_rn(x)) |
           ((uint32_t)__bfloat16_as_ushort(__float2bfloat16_rn(y)) << 16);
}
__device__ __forceinline__ void split2(float x0, float x1, uint32_t& h, uint32_t& l) {
    float h0 = __bfloat162float(__float2bfloat16_rn(x0));
    float h1 = __bfloat162float(__float2bfloat16_rn(x1));
    h = pack_bf2(x0, x1);
    l = pack_bf2(x0 - h0, x1 - h1);
}
__device__ __forceinline__ void store_octet_split(uint32_t* dh, uint32_t* dl,
                                                  float4 v0, float4 v1) {
    float fv[8] = {v0.x, v0.y, v0.z, v0.w, v1.x, v1.y, v1.z, v1.w};
#pragma unroll
    for (int j = 0; j < 4; j++) {
        uint32_t h, l;
        split2(fv[2 * j], fv[2 * j + 1], h, l);
        dh[2 * j] = h;
        dl[2 * j] = l;
    }
}

// ---------------- prep kernels (unchanged, passing) ---------------------------
__global__ void bconv_kernel(const float* __restrict__ Wf) {
    int idx = blockIdx.x * blockDim.x + threadIdx.x;
    if (idx >= BPK_WORDS) return;
    int w   = idx & 7;
    int kb  = (idx >> 3) & 3;
    int tmp = idx >> 5;
    int n   = tmp % 320;
    int c   = tmp / 320;
    int lp  = (w & 1) ? ((w >> 1) + 4) : (w >> 1);
    int k0  = c * 64 + kb * 16 + lp * 2;
    float x0 = 0.f, x1 = 0.f;
    if (n < EMB) {
        x0 = Wf[(size_t)n * FEAT + k0];
        x1 = Wf[(size_t)n * FEAT + k0 + 1];
    }
    uint32_t h, l;
    split2(x0, x1, h, l);
    g_Bh[idx] = h;
    g_Bl[idx] = l;
}

__global__ void fpack_kernel(const float* __restrict__ feature) {
    size_t idx = (size_t)blockIdx.x * blockDim.x + threadIdx.x;
    if (idx >= F_WORDS) return;
    size_t m = idx >> 10;
    int wi = (int)(idx & 1023);
    int c  = wi >> 5;
    int r  = wi & 31;
    int kb = r >> 3;
    int w  = r & 7;
    int lp = (w & 1) ? ((w >> 1) + 4) : (w >> 1);
    int k0 = c * 64 + kb * 16 + lp * 2;
    float x0 = feature[m * FEAT + k0];
    float x1 = feature[m * FEAT + k0 + 1];
    uint32_t h, l;
    split2(x0, x1, h, l);
    g_Fh[idx] = h;
    g_Fl[idx] = l;
}

__global__ void combine_kernel(const float* __restrict__ Wp, const float* __restrict__ bp,
                               const float* __restrict__ Wm, const float* __restrict__ bm)
{
    int idx = blockIdx.x * blockDim.x + threadIdx.x;
    if (idx < WCPK_WORDS) {
        int w   = idx & 7;
        int kb  = (idx >> 3) & 3;
        int tmp = idx >> 5;
        int n   = tmp % 320;
        int c   = tmp / 320;
        int lp  = (w & 1) ? ((w >> 1) + 4) : (w >> 1);
        int k0  = c * 64 + kb * 16 + lp * 2;
        float x0 = 0.f, x1 = 0.f;
        if (n < EMB) {
            if (k0 < EMB)     x0 = Wp[n * EMB + k0]     + 1e-5f * Wm[n * EMB + k0];
            if (k0 + 1 < EMB) x1 = Wp[n * EMB + k0 + 1] + 1e-5f * Wm[n * EMB + k0 + 1];
        }
        uint32_t h, l;
        split2(x0, x1, h, l);
        g_Wch[idx] = h;
        g_Wcl[idx] = l;
    }
    if (idx < NPADB) {
        g_bc[idx] = (idx < EMB) ? (bp[idx] + 1e-5f * bm[idx]) : 0.f;
    }
}

__global__ void wvpack_kernel(const float* __restrict__ wv) {
    size_t idx = (size_t)blockIdx.x * blockDim.x + threadIdx.x;
    if (idx >= WV_WORDS) return;
    int wi = (int)(idx % 160);
    size_t n = idx / 160;
    int c  = wi >> 5;
    int r  = wi & 31;
    int kb = r >> 3;
    int w  = r & 7;
    int lp = (w & 1) ? ((w >> 1) + 4) : (w >> 1);
    int k0 = c * 64 + kb * 16 + lp * 2;
    float x0 = (k0     < EMB) ? wv[n * EMB + k0]     : 0.f;
    float x1 = (k0 + 1 < EMB) ? wv[n * EMB + k0 + 1] : 0.f;
    uint32_t h, l;
    split2(x0, x1, h, l);
    g_wvh[idx] = h;
    g_wvl[idx] = l;
}

// ============= k_emb GEMM: smem-free direct-LDG mma.sync =====================
// grid (2, 128): x = N half, y = M tile. 512 threads = 16 warps (4M x 4N).
// Fragments loaded straight from pre-packed gmem (uint2 per frag):
//   A frag:  Fh2[m*512 + c*16 + kb*4 + q]
//   B frag:  Bh2[(c*320 + n)*16 + kb*4 + q]
// No shared memory, no barriers — warps free-run; L2 serves reuse.
__global__ __launch_bounds__(512)
void kemb_mma_kernel(const float* __restrict__ bf,
                     const float* __restrict__ wv,
                     const int* __restrict__ label,
                     float* __restrict__ C)
{
    const int t    = threadIdx.x;
    const int lane = t & 31;
    const int wid  = t >> 5;             // 0..15
    const int gid  = lane >> 2;
    const int q    = lane & 3;
    const int wm   = (wid & 3) * 32;
    const int wn   = (wid >> 2) * 40;
    const int ny   = blockIdx.x;
    const int m0   = blockIdx.y * 128;

    const uint2* Fh2 = (const uint2*)g_Fh;
    const uint2* Fl2 = (const uint2*)g_Fl;
    const uint2* Bh2 = (const uint2*)g_Bh;
    const uint2* Bl2 = (const uint2*)g_Bl;

    const int r0 = m0 + wm + gid;                 // A row, mf=0 lower
    const int nb0 = ny * 160 + wn + gid;          // B row, f=0

    // invariant uint2 bases (kb/q folded in; c advances by +16 per chunk)
    size_t aBase = (size_t)r0 * 512 + q;          // + mfOff + 8*512 rows + kb*4 + c*16
    size_t bBase = (size_t)nb0 * 16 + q;          // + f*128 + c*5120 + kb*4

    float acc[2][5][4];
#pragma unroll
    for (int mf = 0; mf < 2; mf++)
#pragma unroll
        for (int f = 0; f < 5; f++)
#pragma unroll
            for (int r = 0; r < 4; r++) acc[mf][f][r] = 0.f;

    for (int c = 0; c < 32; c++) {
        const size_t aC = aBase + (size_t)c * 16;
        const size_t bC = bBase + (size_t)c * 5120;
#pragma unroll
        for (int kb = 0; kb < 4; kb++) {
            const size_t aK = aC + kb * 4;
            const size_t bK = bC + kb * 4;
            uint2 ah[2][2], al[2][2];
#pragma unroll
            for (int mf = 0; mf < 2; mf++) {
                size_t ra = aK + (size_t)(mf * 16) * 512;
                ah[mf][0] = Fh2[ra];
                ah[mf][1] = Fh2[ra + 8 * 512];
                al[mf][0] = Fl2[ra];
                al[mf][1] = Fl2[ra + 8 * 512];
            }
            uint2 bh[5], bl[5];
#pragma unroll
            for (int f = 0; f < 5; f++) {
                size_t rb = bK + (size_t)(f * 8) * 16;
                bh[f] = Bh2[rb];
                bl[f] = Bl2[rb];
            }
            // term-major for long same-acc dependency distance
#pragma unroll
            for (int f = 0; f < 5; f++)
#pragma unroll
                for (int mf = 0; mf < 2; mf++)
                    mma_bf16(acc[mf][f], ah[mf][0].x, ah[mf][1].x, ah[mf][0].y, ah[mf][1].y, bh[f].x, bh[f].y);
#pragma unroll
            for (int f = 0; f < 5; f++)
#pragma unroll
                for (int mf = 0; mf < 2; mf++)
                    mma_bf16(acc[mf][f], al[mf][0].x, al[mf][1].x, al[mf][0].y, al[mf][1].y, bh[f].x, bh[f].y);
#pragma unroll
            for (int f = 0; f < 5; f++)
#pragma unroll
                for (int mf = 0; mf < 2; mf++)
                    mma_bf16(acc[mf][f], ah[mf][0].x, ah[mf][1].x, ah[mf][0].y, ah[mf][1].y, bl[f].x, bl[f].y);
        }
    }

#pragma unroll
    for (int mf = 0; mf < 2; mf++) {
        int rr0 = m0 + wm + mf * 16 + gid;
        int rr1 = rr0 + 8;
        const float* w0 = wv + (size_t)label[rr0] * EMB;
        const float* w1 = wv + (size_t)label[rr1] * EMB;
        float* c0p = C + (size_t)rr0 * EMB;
        float* c1p = C + (size_t)rr1 * EMB;
#pragma unroll
        for (int f = 0; f < 5; f++) {
            int n = ny * 160 + wn + f * 8 + q * 2;
            if (n < EMB) {
                float2 bv = *(const float2*)&bf[n];
                float2 o0, o1;
                o0.x = acc[mf][f][0] + bv.x + w0[n];
                o0.y = acc[mf][f][1] + bv.y + w0[n + 1];
                o1.x = acc[mf][f][2] + bv.x + w1[n];
                o1.y = acc[mf][f][3] + bv.y + w1[n + 1];
                *(float2*)&c0p[n] = o0;
                *(float2*)&c1p[n] = o1;
            }
        }
    }
}

// ============= projection GEMM via mma.sync bf16-split (R12, passing) ========
#define ROWB 160
#define BNT  160
#define PSM_AH 0
#define PSM_AL (PSM_AH + 128 * ROWB)
#define PSM_BH (PSM_AL + 128 * ROWB)
#define PSM_BL (PSM_BH + BNT * ROWB)
#define PSM_TOTAL (PSM_BL + BNT * ROWB)      // 92160

__global__ __launch_bounds__(256)
void proj_mma_kernel(const float* __restrict__ P,
                     const float* __restrict__ bias,
                     float* __restrict__ C)
{
    extern __shared__ char smem[];
    const uint32_t sbase = smem_u32(smem);
    const int t    = threadIdx.x;
    const int lane = t & 31;
    const int wid  = t >> 5;
    const int gid  = lane >> 2;
    const int q    = lane & 3;
    const int wm   = (wid & 3) * 32;
    const int wn   = (wid >> 2) * 80;
    const int ny   = blockIdx.x;
    const int m0   = blockIdx.y * 128;

    const uint2* Ah2 = (const uint2*)(smem + PSM_AH);
    const uint2* Al2 = (const uint2*)(smem + PSM_AL);
    const uint2* Bh2 = (const uint2*)(smem + PSM_BH);
    const uint2* Bl2 = (const uint2*)(smem + PSM_BL);

    float acc[2][10][4];
#pragma unroll
    for (int mf = 0; mf < 2; mf++)
#pragma unroll
        for (int f = 0; f < 10; f++)
#pragma unroll
            for (int r = 0; r < 4; r++) acc[mf][f][r] = 0.f;

    for (int c = 0; c < 5; c++) {
        __syncthreads();
#pragma unroll
        for (int i = 0; i < 5; i++) {
            int idx = t + i * 256;
            int n   = idx >> 3;
            int sub = idx & 7;
            int kb  = sub >> 1;
            int h   = sub & 1;
            uint32_t soff = (uint32_t)(n * ROWB + kb * 32 + h * 16);
            size_t   goff = ((((size_t)c * 320 + ny * BNT + n) * 4 + kb) * 8 + h * 4);
            cp16(sbase + PSM_BH + soff, (const char*)g_Wch + goff * 4);
            cp16(sbase + PSM_BL + soff, (const char*)g_Wcl + goff * 4);
        }
        asm volatile("cp.async.commit_group;" ::: "memory");

#pragma unroll
        for (int i = 0; i < 4; i++) {
            int idx = t + i * 256;
            int row = idx >> 3;
            int o   = idx & 7;
            const float4* src = (const float4*)&P[(size_t)(m0 + row) * KPAD + c * 64 + o * 8];
            uint32_t* dh = (uint32_t*)(smem + PSM_AH) + row * 40 + (o >> 1) * 8 + (o & 1);
            uint32_t* dl = (uint32_t*)(smem + PSM_AL) + row * 40 + (o >> 1) * 8 + (o & 1);
            store_octet_split(dh, dl, src[0], src[1]);
        }
        asm volatile("cp.async.wait_group 0;" ::: "memory");
        __syncthreads();

#pragma unroll
        for (int kb = 0; kb < 4; kb++) {
            uint2 ah[2][2], al[2][2];
#pragma unroll
            for (int mf = 0; mf < 2; mf++) {
                int r0 = wm + mf * 16 + gid;
                ah[mf][0] = Ah2[r0 * 20 + kb * 4 + q];
                ah[mf][1] = Ah2[(r0 + 8) * 20 + kb * 4 + q];
                al[mf][0] = Al2[r0 * 20 + kb * 4 + q];
                al[mf][1] = Al2[(r0 + 8) * 20 + kb * 4 + q];
            }
#pragma unroll
            for (int f = 0; f < 10; f++) {
                int nb = wn + f * 8 + gid;
                uint2 bh = Bh2[nb * 20 + kb * 4 + q];
                uint2 bl = Bl2[nb * 20 + kb * 4 + q];
#pragma unroll
                for (int mf = 0; mf < 2; mf++) {
                    mma_bf16(acc[mf][f], ah[mf][0].x, ah[mf][1].x, ah[mf][0].y, ah[mf][1].y, bh.x, bh.y);
                    mma_bf16(acc[mf][f], al[mf][0].x, al[mf][1].x, al[mf][0].y, al[mf][1].y, bh.x, bh.y);
                    mma_bf16(acc[mf][f], ah[mf][0].x, ah[mf][1].x, ah[mf][0].y, ah[mf][1].y, bl.x, bl.y);
                }
            }
        }
    }

#pragma unroll
    for (int mf = 0; mf < 2; mf++) {
        int r0 = m0 + wm + mf * 16 + gid;
        int r1 = r0 + 8;
        float* c0p = C + (size_t)r0 * EMB;
        float* c1p = C + (size_t)r1 * EMB;
#pragma unroll
        for (int f = 0; f < 10; f++) {
            int n = ny * BNT + wn + f * 8 + q * 2;
            if (n < EMB) {
                float2 bv = *(const float2*)&bias[n];
                float2 o0, o1;
                o0.x = acc[mf][f][0] + bv.x;
                o0.y = acc[mf][f][1] + bv.y;
                o1.x = acc[mf][f][2] + bv.x;
                o1.y = acc[mf][f][3] + bv.y;
                *(float2*)&c0p[n] = o0;
                *(float2*)&c1p[n] = o1;
            }
        }
    }
}

// ============= attention via mma.sync; Q from pre-packed wv (R12, passing) ===
#define A_SM_QH 0
#define A_SM_QL (A_SM_QH + 384 * ROWB)
#define A_SM_KH (A_SM_QL + 384 * ROWB)
#define A_SM_KL (A_SM_KH + 64 * ROWB)
#define A_SM_QI (A_SM_KL + 64 * ROWB)
#define A_SM_R  (A_SM_QI + 1536)
#define A_SM_WT (A_SM_R + 1536)
#define A_SM_TOTAL (A_SM_WT + 1536)          // 147968
#define QSTR 68

__global__ __launch_bounds__(384)
void attn_mma_kernel(const float* __restrict__ wv, const int* __restrict__ query,
                     const float* __restrict__ kemb)
{
    extern __shared__ char smem[];
    const uint32_t sbase = smem_u32(smem);
    const int b    = blockIdx.x;
    const int t    = threadIdx.x;
    const int lane = t & 31;
    const int wid  = t >> 5;
    const int gid  = lane >> 2;
    const int q    = lane & 3;
    const int wbase = wid * 32;

    int*   sQi = (int*)(smem + A_SM_QI);
    float* sR  = (float*)(smem + A_SM_R);
    float* sWt = (float*)(smem + A_SM_WT);

    if (t < 384) sQi[t] = query[(size_t)b * NQ * NW + t];
    __syncthreads();

    const uint2* Qh2 = (const uint2*)(smem + A_SM_QH);
    const uint2* Ql2 = (const uint2*)(smem + A_SM_QL);
    const uint2* Kh2 = (const uint2*)(smem + A_SM_KH);
    const uint2* Kl2 = (const uint2*)(smem + A_SM_KL);

    float acc[2][8][4];
#pragma unroll
    for (int mf = 0; mf < 2; mf++)
#pragma unroll
        for (int f = 0; f < 8; f++)
#pragma unroll
            for (int r = 0; r < 4; r++) acc[mf][f][r] = 0.f;

    const float* kbgm = kemb + (size_t)b * NK * EMB;

    for (int c = 0; c < 5; c++) {
        __syncthreads();
#pragma unroll
        for (int i = 0; i < 8; i++) {
            int idx = t + i * 384;
            int row = idx >> 3, s = idx & 7;
            size_t base = (size_t)sQi[row] * 160 + c * 32 + s * 4;
            uint32_t dst = (uint32_t)(row * ROWB + s * 16);
            cp16(sbase + A_SM_QH + dst, (const char*)g_wvh + base * 4);
            cp16(sbase + A_SM_QL + dst, (const char*)g_wvl + base * 4);
        }
        asm volatile("cp.async.commit_group;" ::: "memory");

        for (int idx = t; idx < 64 * 8; idx += 384) {
            int row = idx >> 3, o = idx & 7;
            int f0 = c * 16 + 2 * o;
            float4 v0 = (f0     < 75) ? *(const float4*)&kbgm[row * EMB + 4 * f0]     : make_float4(0,0,0,0);
            float4 v1 = (f0 + 1 < 75) ? *(const float4*)&kbgm[row * EMB + 4 * f0 + 4] : make_float4(0,0,0,0);
            uint32_t* dh = (uint32_t*)(smem + A_SM_KH) + row * 40 + (o >> 1) * 8 + (o & 1);
            uint32_t* dl = (uint32_t*)(smem + A_SM_KL) + row * 40 + (o >> 1) * 8 + (o & 1);
            store_octet_split(dh, dl, v0, v1);
        }
        asm volatile("cp.async.wait_group 0;" ::: "memory");
        __syncthreads();

#pragma unroll
        for (int kb = 0; kb < 4; kb++) {
            uint2 ah[2][2], al[2][2];
#pragma unroll
            for (int mf = 0; mf < 2; mf++) {
                int r0 = wbase + mf * 16 + gid;
                ah[mf][0] = Qh2[r0 * 20 + kb * 4 + q];
                ah[mf][1] = Qh2[(r0 + 8) * 20 + kb * 4 + q];
                al[mf][0] = Ql2[r0 * 20 + kb * 4 + q];
                al[mf][1] = Ql2[(r0 + 8) * 20 + kb * 4 + q];
            }
#pragma unroll
            for (int f = 0; f < 8; f++) {
                int nb = f * 8 + gid;
                uint2 bh = Kh2[nb * 20 + kb * 4 + q];
                uint2 bl = Kl2[nb * 20 + kb * 4 + q];
#pragma unroll
                for (int mf = 0; mf < 2; mf++) {
                    mma_bf16(acc[mf][f], ah[mf][0].x, ah[mf][1].x, ah[mf][0].y, ah[mf][1].y, bh.x, bh.y);
                    mma_bf16(acc[mf][f], al[mf][0].x, al[mf][1].x, al[mf][0].y, al[mf][1].y, bh.x, bh.y);
                    mma_bf16(acc[mf][f], ah[mf][0].x, ah[mf][1].x, ah[mf][0].y, ah[mf][1].y, bl.x, bl.y);
                }
            }
        }
    }

    const float scale = 0.05773502691896258f;
#pragma unroll
    for (int mf = 0; mf < 2; mf++) {
#pragma unroll
        for (int h = 0; h < 2; h++) {
            float vs[16];
            float vmax = -FLT_MAX;
#pragma unroll
            for (int f = 0; f < 8; f++) {
                vs[2 * f]     = acc[mf][f][h * 2]     * scale;
                vs[2 * f + 1] = acc[mf][f][h * 2 + 1] * scale;
                vmax = fmaxf(vmax, fmaxf(vs[2 * f], vs[2 * f + 1]));
            }
            vmax = fmaxf(vmax, __shfl_xor_sync(0xffffffffu, vmax, 1));
            vmax = fmaxf(vmax, __shfl_xor_sync(0xffffffffu, vmax, 2));
            float e = 0.f;
#pragma unroll
            for (int i = 0; i < 16; i++) e += __expf(vs[i] - vmax);
            e += __shfl_xor_sync(0xffffffffu, e, 1);
            e += __shfl_xor_sync(0xffffffffu, e, 2);
            if (q == 0) sR[wbase + mf * 16 + h * 8 + gid] = 1.f / e;
        }
    }
    __syncthreads();

    if (t < 32) {
        float v[NW];
        float m = -FLT_MAX;
#pragma unroll
        for (int w = 0; w < NW; w++) {
            v[w] = (sQi[t * NW + w] == 0) ? -FLT_MAX : sR[t * NW + w];
            m = fmaxf(m, v[w]);
        }
        float s = 0.f;
#pragma unroll
        for (int w = 0; w < NW; w++) { v[w] = __expf(v[w] - m); s += v[w]; }
        float inv = 0.2f / s;
#pragma unroll
        for (int w = 0; w < NW; w++) sWt[t * NW + w] = v[w] * inv;
    }
    __syncthreads();

    float* sQf = (float*)(smem + A_SM_QH);
    for (int c = 0; c < 5; c++) {
        __syncthreads();
        for (int idx = t; idx < 384 * 16; idx += 384) {
            int row = idx >> 4, j = idx & 15;
            int f0 = c * 16 + j;
            float4 v = (f0 < 75) ? *(const float4*)&wv[(size_t)sQi[row] * EMB + 4 * f0]
                                 : make_float4(0, 0, 0, 0);
            *(float4*)&sQf[row * QSTR + 4 * j] = v;
        }
        __syncthreads();
        for (int idx = t; idx < 32 * 64; idx += 384) {
            int qq = idx >> 6, d = idx & 63;
            int dg = c * 64 + d;
            float v = 0.f;
            if (dg < EMB) {
#pragma unroll
                for (int w = 0; w < NW; w++)
                    v += sWt[qq * NW + w] * sQf[(qq * NW + w) * QSTR + d];
            }
            g_P[((size_t)b * NQ + qq) * KPAD + dg] = v;
        }
    }
}

// ---------------- launch ------------------------------------------------------
extern "C" void kernel_launch(void* const* d_in, const int* in_sizes, int n_in,
                              void* d_out, int out_size)
{
    const float* wv      = (const float*)d_in[0];
    const float* Wf      = (const float*)d_in[1];
    const float* bf      = (const float*)d_in[2];
    const float* Wp      = (const float*)d_in[3];
    const float* bp      = (const float*)d_in[4];
    const float* Wm      = (const float*)d_in[5];
    const float* bm      = (const float*)d_in[6];
    const float* feature = (const float*)d_in[7];
    const int*   query   = (const int*)d_in[8];
    const int*   label   = (const int*)d_in[9];

    float* outP = (float*)d_out;
    float* outK = outP + (size_t)BATCH * NQ * EMB;

    void *pP = nullptr, *pbc = nullptr;
    cudaGetSymbolAddress(&pP,  g_P);
    cudaGetSymbolAddress(&pbc, g_bc);

    // 0) weight/wv/feature prep
    combine_kernel<<<(WCPK_WORDS + 255) / 256, 256>>>(Wp, bp, Wm, bm);
    bconv_kernel<<<(BPK_WORDS + 255) / 256, 256>>>(Wf);
    wvpack_kernel<<<(int)((WV_WORDS + 255) / 256), 256>>>(wv);
    fpack_kernel<<<(int)((F_WORDS + 255) / 256), 256>>>(feature);

    // 1) k_emb (smem-free direct-LDG mma)
    {
        dim3 grid(2, (BATCH * NK) / 128);
        kemb_mma_kernel<<<grid, 512>>>(bf, wv, label, outK);
    }

    // 2) attention + pooling
    cudaFuncSetAttribute(attn_mma_kernel,
                         cudaFuncAttributeMaxDynamicSharedMemorySize, A_SM_TOTAL);
    attn_mma_kernel<<<BATCH, 384, A_SM_TOTAL>>>(wv, query, outK);

    // 3) p_emb = P @ Wc^T + bc
    cudaFuncSetAttribute(proj_mma_kernel,
                         cudaFuncAttributeMaxDynamicSharedMemorySize, PSM_TOTAL);
    {
        dim3 grid(2, (BATCH * NQ) / 128);
        proj_mma_kernel<<<grid, 256, PSM_TOTAL>>>((const float*)pP,
                                                  (const float*)pbc, outP);
    }
}

// round 17
// speedup vs baseline: 1.2794x; 1.2794x over previous
#include <cuda_runtime.h>
#include <cuda_bf16.h>
#include <math.h>
#include <float.h>
#include <stdint.h>

#define VOCAB 30000
#define EMB   300
#define FEAT  2048
#define BATCH 256
#define NQ    32
#define NW    12
#define NK    64

#define KPAD  320
#define NPADB 320

// ---------------- scratch (static device globals; no runtime alloc) ----------
__device__ float g_P[(size_t)BATCH * NQ * KPAD];
__device__ float g_bc[NPADB];
#define BPK_WORDS (32 * 320 * 4 * 8)
__device__ __align__(16) uint32_t g_Bh[BPK_WORDS];
__device__ __align__(16) uint32_t g_Bl[BPK_WORDS];
#define WCPK_WORDS (5 * 320 * 4 * 8)
__device__ __align__(16) uint32_t g_Wch[WCPK_WORDS];
__device__ __align__(16) uint32_t g_Wcl[WCPK_WORDS];
#define WV_WORDS ((size_t)VOCAB * 160)
__device__ __align__(16) uint32_t g_wvh[WV_WORDS];
__device__ __align__(16) uint32_t g_wvl[WV_WORDS];

// ======================= portable PTX helpers ================================
__device__ __forceinline__ uint32_t smem_u32(const void* p) {
    uint32_t a;
    asm("{ .reg .u64 t; cvta.to.shared.u64 t, %1; cvt.u32.u64 %0, t; }" : "=r"(a) : "l"(p));
    return a;
}
__device__ __forceinline__ void cp16(uint32_t s, const void* g) {
    asm volatile("cp.async.cg.shared.global [%0], [%1], 16;" :: "r"(s), "l"(g) : "memory");
}
__device__ __forceinline__ void mma_bf16(float* c, uint32_t a0, uint32_t a1,
                                         uint32_t a2, uint32_t a3,
                                         uint32_t b0, uint32_t b1) {
    asm volatile(
        "mma.sync.aligned.m16n8k16.row.col.f32.bf16.bf16.f32 "
        "{%0,%1,%2,%3}, {%4,%5,%6,%7}, {%8,%9}, {%0,%1,%2,%3};"
        : "+f"(c[0]), "+f"(c[1]), "+f"(c[2]), "+f"(c[3])
        : "r"(a0), "r"(a1), "r"(a2), "r"(a3), "r"(b0), "r"(b1));
}
__device__ __forceinline__ uint32_t pack_bf2(float x, float y) {
    return (uint32_t)__bfloat16_as_ushort(__float2bfloat16_rn(x)) |
           ((uint32_t)__bfloat16_as_ushort(__float2bfloat16_rn(y)) << 16);
}
__device__ __forceinline__ void split2(float x0, float x1, uint32_t& h, uint32_t& l) {
    float h0 = __bfloat162float(__float2bfloat16_rn(x0));
    float h1 = __bfloat162float(__float2bfloat16_rn(x1));
    h = pack_bf2(x0, x1);
    l = pack_bf2(x0 - h0, x1 - h1);
}
__device__ __forceinline__ void store_octet_split(uint32_t* dh, uint32_t* dl,
                                                  float4 v0, float4 v1) {
    float fv[8] = {v0.x, v0.y, v0.z, v0.w, v1.x, v1.y, v1.z, v1.w};
#pragma unroll
    for (int j = 0; j < 4; j++) {
        uint32_t h, l;
        split2(fv[2 * j], fv[2 * j + 1], h, l);
        dh[2 * j] = h;
        dl[2 * j] = l;
    }
}

// ---------------- prep kernels (unchanged, passing) ---------------------------
__global__ void bconv_kernel(const float* __restrict__ Wf) {
    int idx = blockIdx.x * blockDim.x + threadIdx.x;
    if (idx >= BPK_WORDS) return;
    int w   = idx & 7;
    int kb  = (idx >> 3) & 3;
    int tmp = idx >> 5;
    int n   = tmp % 320;
    int c   = tmp / 320;
    int lp  = (w & 1) ? ((w >> 1) + 4) : (w >> 1);
    int k0  = c * 64 + kb * 16 + lp * 2;
    float x0 = 0.f, x1 = 0.f;
    if (n < EMB) {
        x0 = Wf[(size_t)n * FEAT + k0];
        x1 = Wf[(size_t)n * FEAT + k0 + 1];
    }
    uint32_t h, l;
    split2(x0, x1, h, l);
    g_Bh[idx] = h;
    g_Bl[idx] = l;
}

__global__ void combine_kernel(const float* __restrict__ Wp, const float* __restrict__ bp,
                               const float* __restrict__ Wm, const float* __restrict__ bm)
{
    int idx = blockIdx.x * blockDim.x + threadIdx.x;
    if (idx < WCPK_WORDS) {
        int w   = idx & 7;
        int kb  = (idx >> 3) & 3;
        int tmp = idx >> 5;
        int n   = tmp % 320;
        int c   = tmp / 320;
        int lp  = (w & 1) ? ((w >> 1) + 4) : (w >> 1);
        int k0  = c * 64 + kb * 16 + lp * 2;
        float x0 = 0.f, x1 = 0.f;
        if (n < EMB) {
            if (k0 < EMB)     x0 = Wp[n * EMB + k0]     + 1e-5f * Wm[n * EMB + k0];
            if (k0 + 1 < EMB) x1 = Wp[n * EMB + k0 + 1] + 1e-5f * Wm[n * EMB + k0 + 1];
        }
        uint32_t h, l;
        split2(x0, x1, h, l);
        g_Wch[idx] = h;
        g_Wcl[idx] = l;
    }
    if (idx < NPADB) {
        g_bc[idx] = (idx < EMB) ? (bp[idx] + 1e-5f * bm[idx]) : 0.f;
    }
}

__global__ void wvpack_kernel(const float* __restrict__ wv) {
    size_t idx = (size_t)blockIdx.x * blockDim.x + threadIdx.x;
    if (idx >= WV_WORDS) return;
    int wi = (int)(idx % 160);
    size_t n = idx / 160;
    int c  = wi >> 5;
    int r  = wi & 31;
    int kb = r >> 3;
    int w  = r & 7;
    int lp = (w & 1) ? ((w >> 1) + 4) : (w >> 1);
    int k0 = c * 64 + kb * 16 + lp * 2;
    float x0 = (k0     < EMB) ? wv[n * EMB + k0]     : 0.f;
    float x1 = (k0 + 1 < EMB) ? wv[n * EMB + k0 + 1] : 0.f;
    uint32_t h, l;
    split2(x0, x1, h, l);
    g_wvh[idx] = h;
    g_wvl[idx] = l;
}

// ============= k_emb GEMM: 512-thread term-major + in-kernel A convert =======
// grid (2, 128): x = N half (adjacent bids share M tile -> L2 reuse of feature),
// y = M tile. 16 warps = 4M x 4N (warp tile 32x40).
// A: register-prefetched 1 chunk ahead, converted to single-stage smem.
// B: pre-packed gmem, cp.async double-buffered.
#define ROWB 160
#define BNT  160
#define SM_AH  0
#define SM_AL  (SM_AH + 128 * ROWB)          // 20480
#define SM_B0H (SM_AL + 128 * ROWB)          // 40960
#define SM_B0L (SM_B0H + BNT * ROWB)         // 66560
#define SM_B1H (SM_B0L + BNT * ROWB)         // 92160
#define SM_B1L (SM_B1H + BNT * ROWB)         // 117760
#define SM_GEMM_TOTAL (SM_B1L + BNT * ROWB)  // 143360

__global__ __launch_bounds__(512)
void kemb_mma_kernel(const float* __restrict__ feature,
                     const float* __restrict__ bf,
                     const float* __restrict__ wv,
                     const int* __restrict__ label,
                     float* __restrict__ C)
{
    extern __shared__ char smem[];
    const uint32_t sbase = smem_u32(smem);
    const int t    = threadIdx.x;
    const int lane = t & 31;
    const int wid  = t >> 5;             // 0..15
    const int gid  = lane >> 2;
    const int q    = lane & 3;
    const int wm   = (wid & 3) * 32;     // 4 M groups
    const int wn   = (wid >> 2) * 40;    // 4 N groups
    const int ny   = blockIdx.x;
    const int m0   = blockIdx.y * 128;

    const uint2* Ah2 = (const uint2*)(smem + SM_AH);
    const uint2* Al2 = (const uint2*)(smem + SM_AL);

    float acc[2][5][4];
#pragma unroll
    for (int mf = 0; mf < 2; mf++)
#pragma unroll
        for (int f = 0; f < 5; f++)
#pragma unroll
            for (int r = 0; r < 4; r++) acc[mf][f][r] = 0.f;

    float4 a4[4];                        // A prefetch regs: 2 octets/thread

#define KEMB_PREFETCH_A(cc) do {                                              \
    _Pragma("unroll")                                                         \
    for (int i = 0; i < 2; i++) {                                             \
        int idx = t + i * 512;               /* 0..1023 */                    \
        int row = idx >> 3, o = idx & 7;                                      \
        const float4* s_ = (const float4*)&feature[(size_t)(m0 + row) * FEAT  \
                                                   + (cc) * 64 + o * 8];      \
        a4[2 * i]     = s_[0];                                                \
        a4[2 * i + 1] = s_[1];                                                \
    } } while (0)

#define KEMB_ISSUE_B(cc, ss) do {                                             \
    uint32_t bh_ = sbase + ((ss) ? SM_B1H : SM_B0H);                          \
    uint32_t bl_ = sbase + ((ss) ? SM_B1L : SM_B0L);                          \
    _Pragma("unroll")                                                         \
    for (int i = 0; i < 3; i++) {                                             \
        int idx = t + i * 512;               /* 0..1279 guarded */            \
        if (idx < 1280) {                                                     \
            int n_  = idx >> 3;                                               \
            int s_  = idx & 7;                                                \
            uint32_t so = (uint32_t)(n_ * ROWB + s_ * 16);                    \
            size_t  gw = (((size_t)(cc) * 320 + ny * BNT + n_) * 32 + s_ * 4);\
            cp16(bh_ + so, (const char*)g_Bh + gw * 4);                       \
            cp16(bl_ + so, (const char*)g_Bl + gw * 4);                       \
        }                                                                     \
    }                                                                         \
    asm volatile("cp.async.commit_group;" ::: "memory");                      \
    } while (0)

    KEMB_PREFETCH_A(0);
    KEMB_ISSUE_B(0, 0);

    for (int c = 0; c < FEAT / 64; c++) {
        const int s = c & 1;
        // convert chunk c's A registers into Ah/Al (prev mma done: trailing sync)
#pragma unroll
        for (int i = 0; i < 2; i++) {
            int idx = t + i * 512;
            int row = idx >> 3, o = idx & 7;
            uint32_t* dh = (uint32_t*)(smem + SM_AH) + row * 40 + (o >> 1) * 8 + (o & 1);
            uint32_t* dl = (uint32_t*)(smem + SM_AL) + row * 40 + (o >> 1) * 8 + (o & 1);
            store_octet_split(dh, dl, a4[2 * i], a4[2 * i + 1]);
        }
        if (c + 1 < FEAT / 64) {
            KEMB_PREFETCH_A(c + 1);          // LDGs drain behind this chunk's mma
            KEMB_ISSUE_B(c + 1, s ^ 1);
            asm volatile("cp.async.wait_group 1;" ::: "memory");   // B[c] arrived
        } else {
            asm volatile("cp.async.wait_group 0;" ::: "memory");
        }
        __syncthreads();

        const uint2* Bh2 = (const uint2*)(smem + (s ? SM_B1H : SM_B0H));
        const uint2* Bl2 = (const uint2*)(smem + (s ? SM_B1L : SM_B0L));
#pragma unroll
        for (int kb = 0; kb < 4; kb++) {
            uint2 ah[2][2], al[2][2];
#pragma unroll
            for (int mf = 0; mf < 2; mf++) {
                int r0 = wm + mf * 16 + gid;
                ah[mf][0] = Ah2[r0 * 20 + kb * 4 + q];
                ah[mf][1] = Ah2[(r0 + 8) * 20 + kb * 4 + q];
                al[mf][0] = Al2[r0 * 20 + kb * 4 + q];
                al[mf][1] = Al2[(r0 + 8) * 20 + kb * 4 + q];
            }
            uint2 bh[5], bl[5];
#pragma unroll
            for (int f = 0; f < 5; f++) {
                int nb = wn + f * 8 + gid;
                bh[f] = Bh2[nb * 20 + kb * 4 + q];
                bl[f] = Bl2[nb * 20 + kb * 4 + q];
            }
            // term-major: same-acc dependency distance = 10 mma
#pragma unroll
            for (int f = 0; f < 5; f++)
#pragma unroll
                for (int mf = 0; mf < 2; mf++)
                    mma_bf16(acc[mf][f], ah[mf][0].x, ah[mf][1].x, ah[mf][0].y, ah[mf][1].y, bh[f].x, bh[f].y);
#pragma unroll
            for (int f = 0; f < 5; f++)
#pragma unroll
                for (int mf = 0; mf < 2; mf++)
                    mma_bf16(acc[mf][f], al[mf][0].x, al[mf][1].x, al[mf][0].y, al[mf][1].y, bh[f].x, bh[f].y);
#pragma unroll
            for (int f = 0; f < 5; f++)
#pragma unroll
                for (int mf = 0; mf < 2; mf++)
                    mma_bf16(acc[mf][f], ah[mf][0].x, ah[mf][1].x, ah[mf][0].y, ah[mf][1].y, bl[f].x, bl[f].y);
        }
        __syncthreads();                     // Ah/Al free for next convert
    }

#pragma unroll
    for (int mf = 0; mf < 2; mf++) {
        int r0 = m0 + wm + mf * 16 + gid;
        int r1 = r0 + 8;
        const float* w0 = wv + (size_t)label[r0] * EMB;
        const float* w1 = wv + (size_t)label[r1] * EMB;
        float* c0p = C + (size_t)r0 * EMB;
        float* c1p = C + (size_t)r1 * EMB;
#pragma unroll
        for (int f = 0; f < 5; f++) {
            int n = ny * BNT + wn + f * 8 + q * 2;
            if (n < EMB) {
                float2 bv = *(const float2*)&bf[n];
                float2 o0, o1;
                o0.x = acc[mf][f][0] + bv.x + w0[n];
                o0.y = acc[mf][f][1] + bv.y + w0[n + 1];
                o1.x = acc[mf][f][2] + bv.x + w1[n];
                o1.y = acc[mf][f][3] + bv.y + w1[n + 1];
                *(float2*)&c0p[n] = o0;
                *(float2*)&c1p[n] = o1;
            }
        }
    }
#undef KEMB_PREFETCH_A
#undef KEMB_ISSUE_B
}

// ============= projection GEMM via mma.sync bf16-split (R12, passing) ========
#define PSM_AH 0
#define PSM_AL (PSM_AH + 128 * ROWB)
#define PSM_BH (PSM_AL + 128 * ROWB)
#define PSM_BL (PSM_BH + BNT * ROWB)
#define PSM_TOTAL (PSM_BL + BNT * ROWB)      // 92160

__global__ __launch_bounds__(256)
void proj_mma_kernel(const float* __restrict__ P,
                     const float* __restrict__ bias,
                     float* __restrict__ C)
{
    extern __shared__ char smem[];
    const uint32_t sbase = smem_u32(smem);
    const int t    = threadIdx.x;
    const int lane = t & 31;
    const int wid  = t >> 5;
    const int gid  = lane >> 2;
    const int q    = lane & 3;
    const int wm   = (wid & 3) * 32;
    const int wn   = (wid >> 2) * 80;
    const int ny   = blockIdx.x;
    const int m0   = blockIdx.y * 128;

    const uint2* Ah2 = (const uint2*)(smem + PSM_AH);
    const uint2* Al2 = (const uint2*)(smem + PSM_AL);
    const uint2* Bh2 = (const uint2*)(smem + PSM_BH);
    const uint2* Bl2 = (const uint2*)(smem + PSM_BL);

    float acc[2][10][4];
#pragma unroll
    for (int mf = 0; mf < 2; mf++)
#pragma unroll
        for (int f = 0; f < 10; f++)
#pragma unroll
            for (int r = 0; r < 4; r++) acc[mf][f][r] = 0.f;

    for (int c = 0; c < 5; c++) {
        __syncthreads();
#pragma unroll
        for (int i = 0; i < 5; i++) {
            int idx = t + i * 256;
            int n   = idx >> 3;
            int sub = idx & 7;
            int kb  = sub >> 1;
            int h   = sub & 1;
            uint32_t soff = (uint32_t)(n * ROWB + kb * 32 + h * 16);
            size_t   goff = ((((size_t)c * 320 + ny * BNT + n) * 4 + kb) * 8 + h * 4);
            cp16(sbase + PSM_BH + soff, (const char*)g_Wch + goff * 4);
            cp16(sbase + PSM_BL + soff, (const char*)g_Wcl + goff * 4);
        }
        asm volatile("cp.async.commit_group;" ::: "memory");

#pragma unroll
        for (int i = 0; i < 4; i++) {
            int idx = t + i * 256;
            int row = idx >> 3;
            int o   = idx & 7;
            const float4* src = (const float4*)&P[(size_t)(m0 + row) * KPAD + c * 64 + o * 8];
            uint32_t* dh = (uint32_t*)(smem + PSM_AH) + row * 40 + (o >> 1) * 8 + (o & 1);
            uint32_t* dl = (uint32_t*)(smem + PSM_AL) + row * 40 + (o >> 1) * 8 + (o & 1);
            store_octet_split(dh, dl, src[0], src[1]);
        }
        asm volatile("cp.async.wait_group 0;" ::: "memory");
        __syncthreads();

#pragma unroll
        for (int kb = 0; kb < 4; kb++) {
            uint2 ah[2][2], al[2][2];
#pragma unroll
            for (int mf = 0; mf < 2; mf++) {
                int r0 = wm + mf * 16 + gid;
                ah[mf][0] = Ah2[r0 * 20 + kb * 4 + q];
                ah[mf][1] = Ah2[(r0 + 8) * 20 + kb * 4 + q];
                al[mf][0] = Al2[r0 * 20 + kb * 4 + q];
                al[mf][1] = Al2[(r0 + 8) * 20 + kb * 4 + q];
            }
#pragma unroll
            for (int f = 0; f < 10; f++) {
                int nb = wn + f * 8 + gid;
                uint2 bh = Bh2[nb * 20 + kb * 4 + q];
                uint2 bl = Bl2[nb * 20 + kb * 4 + q];
#pragma unroll
                for (int mf = 0; mf < 2; mf++) {
                    mma_bf16(acc[mf][f], ah[mf][0].x, ah[mf][1].x, ah[mf][0].y, ah[mf][1].y, bh.x, bh.y);
                    mma_bf16(acc[mf][f], al[mf][0].x, al[mf][1].x, al[mf][0].y, al[mf][1].y, bh.x, bh.y);
                    mma_bf16(acc[mf][f], ah[mf][0].x, ah[mf][1].x, ah[mf][0].y, ah[mf][1].y, bl.x, bl.y);
                }
            }
        }
    }

#pragma unroll
    for (int mf = 0; mf < 2; mf++) {
        int r0 = m0 + wm + mf * 16 + gid;
        int r1 = r0 + 8;
        float* c0p = C + (size_t)r0 * EMB;
        float* c1p = C + (size_t)r1 * EMB;
#pragma unroll
        for (int f = 0; f < 10; f++) {
            int n = ny * BNT + wn + f * 8 + q * 2;
            if (n < EMB) {
                float2 bv = *(const float2*)&bias[n];
                float2 o0, o1;
                o0.x = acc[mf][f][0] + bv.x;
                o0.y = acc[mf][f][1] + bv.y;
                o1.x = acc[mf][f][2] + bv.x;
                o1.y = acc[mf][f][3] + bv.y;
                *(float2*)&c0p[n] = o0;
                *(float2*)&c1p[n] = o1;
            }
        }
    }
}

// ============= attention via mma.sync; Q from pre-packed wv (R12, passing) ===
#define A_SM_QH 0
#define A_SM_QL (A_SM_QH + 384 * ROWB)
#define A_SM_KH (A_SM_QL + 384 * ROWB)
#define A_SM_KL (A_SM_KH + 64 * ROWB)
#define A_SM_QI (A_SM_KL + 64 * ROWB)
#define A_SM_R  (A_SM_QI + 1536)
#define A_SM_WT (A_SM_R + 1536)
#define A_SM_TOTAL (A_SM_WT + 1536)          // 147968
#define QSTR 68

__global__ __launch_bounds__(384)
void attn_mma_kernel(const float* __restrict__ wv, const int* __restrict__ query,
                     const float* __restrict__ kemb)
{
    extern __shared__ char smem[];
    const uint32_t sbase = smem_u32(smem);
    const int b    = blockIdx.x;
    const int t    = threadIdx.x;
    const int lane = t & 31;
    const int wid  = t >> 5;
    const int gid  = lane >> 2;
    const int q    = lane & 3;
    const int wbase = wid * 32;

    int*   sQi = (int*)(smem + A_SM_QI);
    float* sR  = (float*)(smem + A_SM_R);
    float* sWt = (float*)(smem + A_SM_WT);

    if (t < 384) sQi[t] = query[(size_t)b * NQ * NW + t];
    __syncthreads();

    const uint2* Qh2 = (const uint2*)(smem + A_SM_QH);
    const uint2* Ql2 = (const uint2*)(smem + A_SM_QL);
    const uint2* Kh2 = (const uint2*)(smem + A_SM_KH);
    const uint2* Kl2 = (const uint2*)(smem + A_SM_KL);

    float acc[2][8][4];
#pragma unroll
    for (int mf = 0; mf < 2; mf++)
#pragma unroll
        for (int f = 0; f < 8; f++)
#pragma unroll
            for (int r = 0; r < 4; r++) acc[mf][f][r] = 0.f;

    const float* kbgm = kemb + (size_t)b * NK * EMB;

    for (int c = 0; c < 5; c++) {
        __syncthreads();
#pragma unroll
        for (int i = 0; i < 8; i++) {
            int idx = t + i * 384;
            int row = idx >> 3, s = idx & 7;
            size_t base = (size_t)sQi[row] * 160 + c * 32 + s * 4;
            uint32_t dst = (uint32_t)(row * ROWB + s * 16);
            cp16(sbase + A_SM_QH + dst, (const char*)g_wvh + base * 4);
            cp16(sbase + A_SM_QL + dst, (const char*)g_wvl + base * 4);
        }
        asm volatile("cp.async.commit_group;" ::: "memory");

        for (int idx = t; idx < 64 * 8; idx += 384) {
            int row = idx >> 3, o = idx & 7;
            int f0 = c * 16 + 2 * o;
            float4 v0 = (f0     < 75) ? *(const float4*)&kbgm[row * EMB + 4 * f0]     : make_float4(0,0,0,0);
            float4 v1 = (f0 + 1 < 75) ? *(const float4*)&kbgm[row * EMB + 4 * f0 + 4] : make_float4(0,0,0,0);
            uint32_t* dh = (uint32_t*)(smem + A_SM_KH) + row * 40 + (o >> 1) * 8 + (o & 1);
            uint32_t* dl = (uint32_t*)(smem + A_SM_KL) + row * 40 + (o >> 1) * 8 + (o & 1);
            store_octet_split(dh, dl, v0, v1);
        }
        asm volatile("cp.async.wait_group 0;" ::: "memory");
        __syncthreads();

#pragma unroll
        for (int kb = 0; kb < 4; kb++) {
            uint2 ah[2][2], al[2][2];
#pragma unroll
            for (int mf = 0; mf < 2; mf++) {
                int r0 = wbase + mf * 16 + gid;
                ah[mf][0] = Qh2[r0 * 20 + kb * 4 + q];
                ah[mf][1] = Qh2[(r0 + 8) * 20 + kb * 4 + q];
                al[mf][0] = Ql2[r0 * 20 + kb * 4 + q];
                al[mf][1] = Ql2[(r0 + 8) * 20 + kb * 4 + q];
            }
#pragma unroll
            for (int f = 0; f < 8; f++) {
                int nb = f * 8 + gid;
                uint2 bh = Kh2[nb * 20 + kb * 4 + q];
                uint2 bl = Kl2[nb * 20 + kb * 4 + q];
#pragma unroll
                for (int mf = 0; mf < 2; mf++) {
                    mma_bf16(acc[mf][f], ah[mf][0].x, ah[mf][1].x, ah[mf][0].y, ah[mf][1].y, bh.x, bh.y);
                    mma_bf16(acc[mf][f], al[mf][0].x, al[mf][1].x, al[mf][0].y, al[mf][1].y, bh.x, bh.y);
                    mma_bf16(acc[mf][f], ah[mf][0].x, ah[mf][1].x, ah[mf][0].y, ah[mf][1].y, bl.x, bl.y);
                }
            }
        }
    }

    const float scale = 0.05773502691896258f;
#pragma unroll
    for (int mf = 0; mf < 2; mf++) {
#pragma unroll
        for (int h = 0; h < 2; h++) {
            float vs[16];
            float vmax = -FLT_MAX;
#pragma unroll
            for (int f = 0; f < 8; f++) {
                vs[2 * f]     = acc[mf][f][h * 2]     * scale;
                vs[2 * f + 1] = acc[mf][f][h * 2 + 1] * scale;
                vmax = fmaxf(vmax, fmaxf(vs[2 * f], vs[2 * f + 1]));
            }
            vmax = fmaxf(vmax, __shfl_xor_sync(0xffffffffu, vmax, 1));
            vmax = fmaxf(vmax, __shfl_xor_sync(0xffffffffu, vmax, 2));
            float e = 0.f;
#pragma unroll
            for (int i = 0; i < 16; i++) e += __expf(vs[i] - vmax);
            e += __shfl_xor_sync(0xffffffffu, e, 1);
            e += __shfl_xor_sync(0xffffffffu, e, 2);
            if (q == 0) sR[wbase + mf * 16 + h * 8 + gid] = 1.f / e;
        }
    }
    __syncthreads();

    if (t < 32) {
        float v[NW];
        float m = -FLT_MAX;
#pragma unroll
        for (int w = 0; w < NW; w++) {
            v[w] = (sQi[t * NW + w] == 0) ? -FLT_MAX : sR[t * NW + w];
            m = fmaxf(m, v[w]);
        }
        float s = 0.f;
#pragma unroll
        for (int w = 0; w < NW; w++) { v[w] = __expf(v[w] - m); s += v[w]; }
        float inv = 0.2f / s;
#pragma unroll
        for (int w = 0; w < NW; w++) sWt[t * NW + w] = v[w] * inv;
    }
    __syncthreads();

    float* sQf = (float*)(smem + A_SM_QH);
    for (int c = 0; c < 5; c++) {
        __syncthreads();
        for (int idx = t; idx < 384 * 16; idx += 384) {
            int row = idx >> 4, j = idx & 15;
            int f0 = c * 16 + j;
            float4 v = (f0 < 75) ? *(const float4*)&wv[(size_t)sQi[row] * EMB + 4 * f0]
                                 : make_float4(0, 0, 0, 0);
            *(float4*)&sQf[row * QSTR + 4 * j] = v;
        }
        __syncthreads();
        for (int idx = t; idx < 32 * 64; idx += 384) {
            int qq = idx >> 6, d = idx & 63;
            int dg = c * 64 + d;
            float v = 0.f;
            if (dg < EMB) {
#pragma unroll
                for (int w = 0; w < NW; w++)
                    v += sWt[qq * NW + w] * sQf[(qq * NW + w) * QSTR + d];
            }
            g_P[((size_t)b * NQ + qq) * KPAD + dg] = v;
        }
    }
}

// ---------------- launch ------------------------------------------------------
extern "C" void kernel_launch(void* const* d_in, const int* in_sizes, int n_in,
                              void* d_out, int out_size)
{
    const float* wv      = (const float*)d_in[0];
    const float* Wf      = (const float*)d_in[1];
    const float* bf      = (const float*)d_in[2];
    const float* Wp      = (const float*)d_in[3];
    const float* bp      = (const float*)d_in[4];
    const float* Wm      = (const float*)d_in[5];
    const float* bm      = (const float*)d_in[6];
    const float* feature = (const float*)d_in[7];
    const int*   query   = (const int*)d_in[8];
    const int*   label   = (const int*)d_in[9];

    float* outP = (float*)d_out;
    float* outK = outP + (size_t)BATCH * NQ * EMB;

    void *pP = nullptr, *pbc = nullptr;
    cudaGetSymbolAddress(&pP,  g_P);
    cudaGetSymbolAddress(&pbc, g_bc);

    // 0) weight/wv prep (no fpack)
    combine_kernel<<<(WCPK_WORDS + 255) / 256, 256>>>(Wp, bp, Wm, bm);
    bconv_kernel<<<(BPK_WORDS + 255) / 256, 256>>>(Wf);
    wvpack_kernel<<<(int)((WV_WORDS + 255) / 256), 256>>>(wv);

    // 1) k_emb (512 threads, term-major, in-kernel A convert, B dbuf)
    cudaFuncSetAttribute(kemb_mma_kernel,
                         cudaFuncAttributeMaxDynamicSharedMemorySize, SM_GEMM_TOTAL);
    {
        dim3 grid(2, (BATCH * NK) / 128);
        kemb_mma_kernel<<<grid, 512, SM_GEMM_TOTAL>>>(feature, bf, wv, label, outK);
    }

    // 2) attention + pooling
    cudaFuncSetAttribute(attn_mma_kernel,
                         cudaFuncAttributeMaxDynamicSharedMemorySize, A_SM_TOTAL);
    attn_mma_kernel<<<BATCH, 384, A_SM_TOTAL>>>(wv, query, outK);

    // 3) p_emb = P @ Wc^T + bc
    cudaFuncSetAttribute(proj_mma_kernel,
                         cudaFuncAttributeMaxDynamicSharedMemorySize, PSM_TOTAL);
    {
        dim3 grid(2, (BATCH * NQ) / 128);
        proj_mma_kernel<<<grid, 256, PSM_TOTAL>>>((const float*)pP,
                                                  (const float*)pbc, outP);
    }
}